// round 12
// baseline (speedup 1.0000x reference)
#include <cuda_runtime.h>
#include <cuda_bf16.h>
#include <cstdint>
#include <cstddef>

// ---------------------------------------------------------------------------
// Problem constants
// ---------------------------------------------------------------------------
#define S_LEN   1500
#define N_STATE 1280
#define N_HEAD  20
#define D_HEAD  64
#define N_MLP   5120
#define NKT     24          // key tiles of 64

// ---------------------------------------------------------------------------
// Scratch (static device memory; no allocations anywhere)
// ---------------------------------------------------------------------------
struct Scratch {
    float h    [S_LEN * N_STATE];
    float q    [S_LEN * N_STATE];
    float k    [S_LEN * N_STATE];
    float v    [S_LEN * N_STATE];
    float attn [S_LEN * N_STATE];
    float x1   [S_LEN * N_STATE];
    float h2   [S_LEN * N_MLP];
    float part0[S_LEN * N_STATE];
    float part1[S_LEN * N_STATE];
};
__device__ Scratch g_scratch;

// ---------------------------------------------------------------------------
// Helpers
// ---------------------------------------------------------------------------
__device__ __forceinline__ uint32_t f2tf(float x) {
    uint32_t r;
    asm("cvt.rna.tf32.f32 %0, %1;" : "=r"(r) : "f"(x));
    return r;
}
__device__ __forceinline__ float rnd_tf(float x) {
    return __uint_as_float(f2tf(x));
}

// D = A(16x8, tf32, row) * B(8x8, tf32, col) + C, fp32 accum. In-place on acc.
__device__ __forceinline__ void mma_tf32(float acc[4], const uint32_t a[4], const uint32_t b[2]) {
    asm volatile(
        "mma.sync.aligned.m16n8k8.row.col.f32.tf32.tf32.f32 "
        "{%0,%1,%2,%3}, {%4,%5,%6,%7}, {%8,%9}, {%0,%1,%2,%3};\n"
        : "+f"(acc[0]), "+f"(acc[1]), "+f"(acc[2]), "+f"(acc[3])
        : "r"(a[0]), "r"(a[1]), "r"(a[2]), "r"(a[3]),
          "r"(b[0]), "r"(b[1]));
}

__device__ __forceinline__ void cp16(uint32_t dst, const float* src, bool ok) {
    int n = ok ? 16 : 0;   // zfill when out of range
    asm volatile("cp.async.cg.shared.global [%0], [%1], 16, %2;\n"
                 :: "r"(dst), "l"(src), "r"(n));
}
#define CP_COMMIT() asm volatile("cp.async.commit_group;\n")
#define CP_WAIT(N)  asm volatile("cp.async.wait_group %0;\n" :: "n"(N))

__device__ __forceinline__ float gelu_exact(float x) {
    return 0.5f * x * (1.0f + erff(x * 0.7071067811865475f));
}

// ---------------------------------------------------------------------------
// LayerNorm: one block per row, 256 threads, C = 1280 = 5*256.
// Output rounded to tf32 (RNA) — consumed only as GEMM A operand.
// ---------------------------------------------------------------------------
__global__ void ln_kernel(const float* __restrict__ x,
                          const float* __restrict__ gamma,
                          const float* __restrict__ beta,
                          float* __restrict__ out) {
    int row = blockIdx.x;
    int tid = threadIdx.x;
    const float* xr = x + (size_t)row * N_STATE;
    float* orow = out + (size_t)row * N_STATE;

    __shared__ float red[256];
    float local[5];
    float s = 0.f;
#pragma unroll
    for (int i = 0; i < 5; i++) { local[i] = xr[tid + i * 256]; s += local[i]; }
    red[tid] = s; __syncthreads();
#pragma unroll
    for (int o = 128; o > 0; o >>= 1) {
        if (tid < o) red[tid] += red[tid + o];
        __syncthreads();
    }
    float mu = red[0] * (1.0f / N_STATE);
    __syncthreads();

    float vs = 0.f;
#pragma unroll
    for (int i = 0; i < 5; i++) { float d = local[i] - mu; vs += d * d; }
    red[tid] = vs; __syncthreads();
#pragma unroll
    for (int o = 128; o > 0; o >>= 1) {
        if (tid < o) red[tid] += red[tid + o];
        __syncthreads();
    }
    float inv = rsqrtf(red[0] * (1.0f / N_STATE) + 1e-5f);

#pragma unroll
    for (int i = 0; i < 5; i++) {
        int c = tid + i * 256;
        orow[c] = rnd_tf((local[i] - mu) * inv * gamma[c] + beta[c]);
    }
}

// ---------------------------------------------------------------------------
// Fused split-K reduce + LayerNorm (one row per block):
//   x1 = p0 + p1 + bias + res            (written out: residual for later)
//   h  = rnd_tf(LN(x1) * gamma + beta)   (written out: next GEMM's A operand)
// ---------------------------------------------------------------------------
__global__ void reduce_ln_kernel(const float* __restrict__ p0,
                                 const float* __restrict__ p1,
                                 const float* __restrict__ bias,
                                 const float* __restrict__ res,
                                 const float* __restrict__ gamma,
                                 const float* __restrict__ beta,
                                 float* __restrict__ x1,
                                 float* __restrict__ h) {
    int row = blockIdx.x;
    int tid = threadIdx.x;
    size_t off = (size_t)row * N_STATE;

    __shared__ float red[256];
    float local[5];
    float s = 0.f;
#pragma unroll
    for (int i = 0; i < 5; i++) {
        int c = tid + i * 256;
        float v = p0[off + c] + p1[off + c] + bias[c] + res[off + c];
        x1[off + c] = v;
        local[i] = v;
        s += v;
    }
    red[tid] = s; __syncthreads();
#pragma unroll
    for (int o = 128; o > 0; o >>= 1) {
        if (tid < o) red[tid] += red[tid + o];
        __syncthreads();
    }
    float mu = red[0] * (1.0f / N_STATE);
    __syncthreads();

    float vs = 0.f;
#pragma unroll
    for (int i = 0; i < 5; i++) { float d = local[i] - mu; vs += d * d; }
    red[tid] = vs; __syncthreads();
#pragma unroll
    for (int o = 128; o > 0; o >>= 1) {
        if (tid < o) red[tid] += red[tid + o];
        __syncthreads();
    }
    float inv = rsqrtf(red[0] * (1.0f / N_STATE) + 1e-5f);

#pragma unroll
    for (int i = 0; i < 5; i++) {
        int c = tid + i * 256;
        h[off + c] = rnd_tf((local[i] - mu) * inv * gamma[c] + beta[c]);
    }
}

// ---------------------------------------------------------------------------
// tf32 MMA GEMM, batched over blockIdx.z:
//   batch mode (aOffK=0): C_z = act(A @ B_z + bias_z), z = different weights
//   split-K mode (aOffK>0): C_z = A[:, z*aOffK:(z+1)*aOffK] @ B_z (partials)
// BM=128, BN=128, BK=32; *** 128 threads = 4 warps (2m x 2n), warp tile
// 64x64 ***. LDS/MMA = 1.0 (was 1.5) and __launch_bounds__(128,2) gives each
// thread a 256-reg budget (acc=128 + frags + addressing ~185), letting ptxas
// pipeline fragment loads under the MMAs. 2 CTAs/SM as before (8 warps/SM).
// 3-stage cp.async pipeline, ONE __syncthreads per 32-deep k-slab.
// A fragments: scalar LDS of raw bits (producers pre-round to tf32).
// B fragments: RNA-converted in-loop.
//   As stride 36: frag banks (36g+t)%32 = (4g+t)  -> conflict-free
//   Bs stride 136: frag banks (136t+g)%32 = (8t+g) -> conflict-free
//   (wn*64 is 0 mod 32 banks -> pattern unchanged across warps)
// ---------------------------------------------------------------------------
#define G_BM 128
#define G_BN 128
#define G_BK 32
#define AS_STRIDE 36
#define BS_STRIDE 136
#define AS_BUF (G_BM * AS_STRIDE)                      // 4608 words
#define BS_BUF (G_BK * BS_STRIDE)                      // 4352 words
#define STAGE_W (AS_BUF + BS_BUF)                      // 8960 words
#define GEMM_SMEM_BYTES (3 * STAGE_W * 4)              // 107520

struct GemmBatch {
    const float* B[3];
    const float* bias[3];
    float*       C[3];
};

__global__ __launch_bounds__(128, 2)
void gemm_tf32(const float* __restrict__ A, GemmBatch args,
               int M, int N, int K, int lda, int aOffK, int act, int rnd) {
    extern __shared__ uint32_t sm[];

    int z = blockIdx.z;
    const float* __restrict__ Bp   = args.B[z];
    const float* __restrict__ bias = args.bias[z];
    float* __restrict__       C    = args.C[z];

    int tid  = threadIdx.x;
    int warp = tid >> 5, lane = tid & 31;
    int g = lane >> 2, t = lane & 3;
    int wm = warp >> 1;       // 0..1 -> rows wm*64
    int wn = warp & 1;        // 0..1 -> cols wn*64
    int bm0 = blockIdx.y * G_BM;
    int bn0 = blockIdx.x * G_BN;

    uint32_t sbase = (uint32_t)__cvta_generic_to_shared(sm);

    // cp.async mappings (128 threads)
    int larow = tid >> 3;          // 0..15 (+16*i, i<8)
    int lacol = (tid & 7) * 4;     // k offset
    int lbrow = tid >> 5;          // 0..3  (+4*i, i<8)
    int lbcol = (tid & 31) * 4;    // n offset

    const float* aptr = A + (size_t)(bm0 + larow) * lda + (size_t)z * aOffK + lacol;
    const float* bptr = Bp + (size_t)lbrow * N + bn0 + lbcol;

    auto loadg = [&](int k0, int stg) {
        uint32_t ad = sbase + (stg * STAGE_W) * 4;
#pragma unroll
        for (int i = 0; i < 8; i++) {
            int r = bm0 + larow + 16 * i;
            cp16(ad + ((larow + 16 * i) * AS_STRIDE + lacol) * 4,
                 aptr + (size_t)(16 * i) * lda + k0, r < M);
        }
        uint32_t bd = ad + AS_BUF * 4;
#pragma unroll
        for (int i = 0; i < 8; i++) {
            cp16(bd + ((lbrow + 4 * i) * BS_STRIDE + lbcol) * 4,
                 bptr + (size_t)(k0 + 4 * i) * N, true);
        }
        CP_COMMIT();
    };

    float acc[4][8][4];
#pragma unroll
    for (int i = 0; i < 4; i++)
#pragma unroll
        for (int j = 0; j < 8; j++)
#pragma unroll
            for (int r = 0; r < 4; r++) acc[i][j][r] = 0.f;

    int nk = K / G_BK;
    loadg(0, 0);
    if (nk > 1) loadg(G_BK, 1);

    int stg = 0;
    for (int kt = 0; kt < nk; kt++) {
        if (kt + 1 < nk) { CP_WAIT(1); }
        else             { CP_WAIT(0); }
        __syncthreads();   // stage kt ready; all warps done with stage kt-1
        if (kt + 2 < nk) {
            int ns = stg + 2; if (ns >= 3) ns -= 3;
            loadg((kt + 2) * G_BK, ns);
        }

        const uint32_t* ab = sm + stg * STAGE_W;
        const uint32_t* bb = ab + AS_BUF;
#pragma unroll
        for (int ks = 0; ks < 4; ks++) {
            uint32_t af[4][4], bf[8][2];
#pragma unroll
            for (int i = 0; i < 4; i++) {
                const uint32_t* base = ab + (wm * 64 + i * 16 + g) * AS_STRIDE + ks * 8 + t;
                af[i][0] = base[0];
                af[i][1] = base[8 * AS_STRIDE];
                af[i][2] = base[4];
                af[i][3] = base[8 * AS_STRIDE + 4];
            }
#pragma unroll
            for (int j = 0; j < 8; j++) {
                const uint32_t* base = bb + (ks * 8 + t) * BS_STRIDE + wn * 64 + j * 8 + g;
                bf[j][0] = f2tf(__uint_as_float(base[0]));
                bf[j][1] = f2tf(__uint_as_float(base[4 * BS_STRIDE]));
            }
#pragma unroll
            for (int i = 0; i < 4; i++)
#pragma unroll
                for (int j = 0; j < 8; j++)
                    mma_tf32(acc[i][j], af[i], bf[j]);
        }
        if (++stg == 3) stg = 0;
    }

    // epilogue
#pragma unroll
    for (int i = 0; i < 4; i++) {
        int r0 = bm0 + wm * 64 + i * 16 + g;
        int r1 = r0 + 8;
#pragma unroll
        for (int j = 0; j < 8; j++) {
            int c = bn0 + wn * 64 + j * 8 + 2 * t;
            float bb0 = bias ? bias[c]     : 0.f;
            float bb1 = bias ? bias[c + 1] : 0.f;
            if (r0 < M) {
                float v0 = acc[i][j][0] + bb0, v1 = acc[i][j][1] + bb1;
                if (act) { v0 = gelu_exact(v0); v1 = gelu_exact(v1); }
                if (rnd) { v0 = rnd_tf(v0); v1 = rnd_tf(v1); }
                *(float2*)&C[(size_t)r0 * N + c] = make_float2(v0, v1);
            }
            if (r1 < M) {
                float v2 = acc[i][j][2] + bb0, v3 = acc[i][j][3] + bb1;
                if (act) { v2 = gelu_exact(v2); v3 = gelu_exact(v3); }
                if (rnd) { v2 = rnd_tf(v2); v3 = rnd_tf(v3); }
                *(float2*)&C[(size_t)r1 * N + c] = make_float2(v2, v3);
            }
        }
    }
}

// ---------------------------------------------------------------------------
// Split-K reduce: out = p0 + p1 + bias + res   (N = N_STATE columns)
// ---------------------------------------------------------------------------
__global__ void splitk_reduce(const float* __restrict__ p0,
                              const float* __restrict__ p1,
                              const float* __restrict__ bias,
                              const float* __restrict__ res,
                              float* __restrict__ out) {
    int i = blockIdx.x * blockDim.x + threadIdx.x;           // float4 index
    const int total4 = S_LEN * N_STATE / 4;
    if (i >= total4) return;
    float4 a = ((const float4*)p0)[i];
    float4 b = ((const float4*)p1)[i];
    float4 r = ((const float4*)res)[i];
    int c = (i * 4) % N_STATE;
    float4 bb = *(const float4*)&bias[c];
    float4 o;
    o.x = a.x + b.x + bb.x + r.x;
    o.y = a.y + b.y + bb.y + r.y;
    o.z = a.z + b.z + bb.z + r.z;
    o.w = a.w + b.w + bb.w + r.w;
    ((float4*)out)[i] = o;
}

// ---------------------------------------------------------------------------
// Fused flash attention (non-causal), k-dim permutation trick. (unchanged)
// Block = (q-tile of 128, head), 256 threads = 8 warps, warp owns 16 q rows.
//  * QK^T: Q frags load dims (2t, 2t+1); K B-frags = one LDS.64 whose halves
//    land directly in bf[0]/bf[1] (operand order -> no repack).
//  * P.V : S/P C-fragment IS the PV A-fragment (P never touches smem).
// Double-buffered K/V via cp.async; one __syncthreads per tile.
// smem = 2*64*72 + 2*64*68 words = 71680 B -> 2 CTAs/SM.
// ---------------------------------------------------------------------------
#define KB_STRIDE 72
#define VB_STRIDE 68
#define KBUF_W (64 * KB_STRIDE)               // 4608
#define VBUF_W (64 * VB_STRIDE)               // 4352
#define ATTN_SMEM_BYTES ((2 * KBUF_W + 2 * VBUF_W) * 4)   // 71680

__global__ __launch_bounds__(256, 2)
void attn_kernel(const float* __restrict__ qp, const float* __restrict__ kp,
                 const float* __restrict__ vp, float* __restrict__ out) {
    extern __shared__ uint32_t smn[];

    int qt = blockIdx.x;
    int h  = blockIdx.y;
    int tid = threadIdx.x, warp = tid >> 5, lane = tid & 31;
    int g = lane >> 2, t = lane & 3;
    int qrow0 = qt * 128 + warp * 16;
    uint32_t sbase = (uint32_t)__cvta_generic_to_shared(smn);

    // ---- preload Q fragments with permuted k: word0<->dim 2t, word2<->2t+1 ----
    uint32_t qf[8][4];
    {
        int rA = qrow0 + g, rB = qrow0 + g + 8;
        bool okA = rA < S_LEN, okB = rB < S_LEN;
        const float* qA = qp + (size_t)rA * N_STATE + h * D_HEAD;
        const float* qB = qp + (size_t)rB * N_STATE + h * D_HEAD;
#pragma unroll
        for (int ks = 0; ks < 8; ks++) {
            int d0 = ks * 8 + 2 * t;
            float a0 = okA ? qA[d0]     : 0.f;
            float a1 = okB ? qB[d0]     : 0.f;
            float a2 = okA ? qA[d0 + 1] : 0.f;
            float a3 = okB ? qB[d0 + 1] : 0.f;
            qf[ks][0] = __float_as_uint(a0 * 0.125f);
            qf[ks][1] = __float_as_uint(a1 * 0.125f);
            qf[ks][2] = __float_as_uint(a2 * 0.125f);
            qf[ks][3] = __float_as_uint(a3 * 0.125f);
        }
    }

    float of[8][4];
#pragma unroll
    for (int j = 0; j < 8; j++)
#pragma unroll
        for (int r = 0; r < 4; r++) of[j][r] = 0.f;
    float m0 = -1e30f, m1 = -1e30f, l0 = 0.f, l1 = 0.f;

    int lrow = tid >> 4;            // 0..15
    int lc4  = (tid & 15) * 4;      // 0..60
    const float* kpb = kp + h * D_HEAD + lc4;
    const float* vpb = vp + h * D_HEAD + lc4;

    auto issue = [&](int kt, int buf) {
#pragma unroll
        for (int p = 0; p < 4; p++) {
            int row = lrow + p * 16;
            int gk = kt * 64 + row;
            cp16(sbase + (buf * KBUF_W + row * KB_STRIDE + lc4) * 4,
                 kpb + (size_t)gk * N_STATE, gk < S_LEN);
        }
#pragma unroll
        for (int p = 0; p < 4; p++) {
            int row = lrow + p * 16;
            int gk = kt * 64 + row;
            cp16(sbase + (2 * KBUF_W + buf * VBUF_W + row * VB_STRIDE + lc4) * 4,
                 vpb + (size_t)gk * N_STATE, gk < S_LEN);
        }
        CP_COMMIT();
    };

    issue(0, 0);

    for (int kt = 0; kt < NKT; kt++) {
        int buf = kt & 1;
        CP_WAIT(0);          // current tile resident
        __syncthreads();     // all warps done with previous tile's buffers
        if (kt + 1 < NKT) issue(kt + 1, buf ^ 1);   // prefetch overlaps compute

        const uint32_t* Kb = smn + buf * KBUF_W;
        const uint32_t* Vb = smn + 2 * KBUF_W + buf * VBUF_W;

        // ---- S = Q * K^T  (16 x 64 per warp); B-frag = one LDS.64 ----
        float sacc[8][4];
#pragma unroll
        for (int j = 0; j < 8; j++)
#pragma unroll
            for (int r = 0; r < 4; r++) sacc[j][r] = 0.f;

#pragma unroll
        for (int ks = 0; ks < 8; ks++) {
#pragma unroll
            for (int j = 0; j < 8; j++) {
                uint2 kb = *(const uint2*)&Kb[(j * 8 + g) * KB_STRIDE + ks * 8 + 2 * t];
                uint32_t bf[2] = {kb.x, kb.y};
                mma_tf32(sacc[j], qf[ks], bf);
            }
        }

        // ---- mask padded keys (only last tile) ----
        if (kt == NKT - 1) {
#pragma unroll
            for (int j = 0; j < 8; j++) {
                int c = j * 8 + 2 * t;
                if (1472 + c     >= S_LEN) { sacc[j][0] = -1e30f; sacc[j][2] = -1e30f; }
                if (1472 + c + 1 >= S_LEN) { sacc[j][1] = -1e30f; sacc[j][3] = -1e30f; }
            }
        }

        // ---- online softmax ----
        float tm0 = -1e30f, tm1 = -1e30f;
#pragma unroll
        for (int j = 0; j < 8; j++) {
            tm0 = fmaxf(tm0, fmaxf(sacc[j][0], sacc[j][1]));
            tm1 = fmaxf(tm1, fmaxf(sacc[j][2], sacc[j][3]));
        }
        tm0 = fmaxf(tm0, __shfl_xor_sync(0xffffffffu, tm0, 1));
        tm0 = fmaxf(tm0, __shfl_xor_sync(0xffffffffu, tm0, 2));
        tm1 = fmaxf(tm1, __shfl_xor_sync(0xffffffffu, tm1, 1));
        tm1 = fmaxf(tm1, __shfl_xor_sync(0xffffffffu, tm1, 2));

        float nm0 = fmaxf(m0, tm0), nm1 = fmaxf(m1, tm1);
        float c0 = __expf(m0 - nm0), c1 = __expf(m1 - nm1);
        l0 *= c0; l1 *= c1;
#pragma unroll
        for (int j = 0; j < 8; j++) {
            of[j][0] *= c0; of[j][1] *= c0;
            of[j][2] *= c1; of[j][3] *= c1;
        }
        m0 = nm0; m1 = nm1;

        // ---- P = exp(S - m), tf32-rounded, kept in the sacc registers ----
        float ps0 = 0.f, ps1 = 0.f;
#pragma unroll
        for (int j = 0; j < 8; j++) {
            float p0 = rnd_tf(__expf(sacc[j][0] - nm0));
            float p1 = rnd_tf(__expf(sacc[j][1] - nm0));
            float p2 = rnd_tf(__expf(sacc[j][2] - nm1));
            float p3 = rnd_tf(__expf(sacc[j][3] - nm1));
            sacc[j][0] = p0; sacc[j][1] = p1; sacc[j][2] = p2; sacc[j][3] = p3;
            ps0 += p0 + p1; ps1 += p2 + p3;
        }
        ps0 += __shfl_xor_sync(0xffffffffu, ps0, 1);
        ps0 += __shfl_xor_sync(0xffffffffu, ps0, 2);
        ps1 += __shfl_xor_sync(0xffffffffu, ps1, 1);
        ps1 += __shfl_xor_sync(0xffffffffu, ps1, 2);
        l0 += ps0; l1 += ps1;

        // ---- O += P * V : A-fragment comes straight from sacc registers ----
#pragma unroll
        for (int ksJ = 0; ksJ < 8; ksJ++) {     // key block = S column block
            uint32_t af[4];
            af[0] = __float_as_uint(sacc[ksJ][0]);   // P[g   ][key 2t]
            af[1] = __float_as_uint(sacc[ksJ][2]);   // P[g+8 ][key 2t]
            af[2] = __float_as_uint(sacc[ksJ][1]);   // P[g   ][key 2t+1]
            af[3] = __float_as_uint(sacc[ksJ][3]);   // P[g+8 ][key 2t+1]
            const uint32_t* vrow = Vb + (ksJ * 8 + 2 * t) * VB_STRIDE + g;
#pragma unroll
            for (int j = 0; j < 8; j++) {
                uint32_t bf[2];
                bf[0] = vrow[j * 8];                 // V[key 2t  ][dim j8+g]
                bf[1] = vrow[VB_STRIDE + j * 8];     // V[key 2t+1][dim j8+g]
                mma_tf32(of[j], af, bf);
            }
        }
    }

    // ---- finalize + store (rounded: feeds O-proj as A operand) ----
    float inv0 = 1.0f / l0, inv1 = 1.0f / l1;
    int r0 = qrow0 + g, r1 = qrow0 + g + 8;
#pragma unroll
    for (int j = 0; j < 8; j++) {
        int c = h * D_HEAD + j * 8 + 2 * t;
        if (r0 < S_LEN)
            *(float2*)&out[(size_t)r0 * N_STATE + c] =
                make_float2(rnd_tf(of[j][0] * inv0), rnd_tf(of[j][1] * inv0));
        if (r1 < S_LEN)
            *(float2*)&out[(size_t)r1 * N_STATE + c] =
                make_float2(rnd_tf(of[j][2] * inv1), rnd_tf(of[j][3] * inv1));
    }
}

// ---------------------------------------------------------------------------
// Launch: 8 kernels on the default stream (graph-capturable, alloc-free)
// ---------------------------------------------------------------------------
extern "C" void kernel_launch(void* const* d_in, const int* in_sizes, int n_in,
                              void* d_out, int out_size) {
    (void)in_sizes; (void)n_in; (void)out_size;

    const float* x    = (const float*)d_in[0];
    const float* Wq   = (const float*)d_in[1];
    const float* bq   = (const float*)d_in[2];
    const float* Wk   = (const float*)d_in[3];
    const float* Wv   = (const float*)d_in[4];
    const float* bv   = (const float*)d_in[5];
    const float* Wo   = (const float*)d_in[6];
    const float* bo   = (const float*)d_in[7];
    const float* ln1g = (const float*)d_in[8];
    const float* ln1b = (const float*)d_in[9];
    const float* ln2g = (const float*)d_in[10];
    const float* ln2b = (const float*)d_in[11];
    const float* W1   = (const float*)d_in[12];
    const float* b1   = (const float*)d_in[13];
    const float* W2   = (const float*)d_in[14];
    const float* b2   = (const float*)d_in[15];
    float* out = (float*)d_out;

    Scratch* sc = nullptr;
    cudaGetSymbolAddress((void**)&sc, g_scratch);

    cudaFuncSetAttribute(gemm_tf32,
                         cudaFuncAttributeMaxDynamicSharedMemorySize,
                         GEMM_SMEM_BYTES);
    cudaFuncSetAttribute(attn_kernel,
                         cudaFuncAttributeMaxDynamicSharedMemorySize,
                         ATTN_SMEM_BYTES);

    dim3 gQKV (N_STATE / G_BN, (S_LEN + G_BM - 1) / G_BM, 3);  // (10,12,3)
    dim3 gSpl (N_STATE / G_BN, (S_LEN + G_BM - 1) / G_BM, 2);  // (10,12,2)
    dim3 gMLP1(N_MLP  / G_BN, (S_LEN + G_BM - 1) / G_BM, 1);   // (40,12,1)
    const int red_grid = (S_LEN * N_STATE / 4 + 255) / 256;

    // LN1 (output tf32-rounded)
    ln_kernel<<<S_LEN, 256>>>(x, ln1g, ln1b, sc->h);

    // QKV projections (one fused launch, shared A; outputs tf32-rounded)
    GemmBatch qkv;
    qkv.B[0] = Wq; qkv.bias[0] = bq;      qkv.C[0] = sc->q;
    qkv.B[1] = Wk; qkv.bias[1] = nullptr; qkv.C[1] = sc->k;
    qkv.B[2] = Wv; qkv.bias[2] = bv;      qkv.C[2] = sc->v;
    gemm_tf32<<<gQKV, 128, GEMM_SMEM_BYTES>>>(sc->h, qkv,
        S_LEN, N_STATE, N_STATE, /*lda=*/N_STATE, /*aOffK=*/0, 0, /*rnd=*/1);

    // attention (output tf32-rounded)
    attn_kernel<<<dim3(12, N_HEAD), 256, ATTN_SMEM_BYTES>>>(sc->q, sc->k, sc->v, sc->attn);

    // O-proj split-K x2 -> partials, then fused reduce(+bias+residual)+LN2
    GemmBatch opr;
    opr.B[0] = Wo;                         opr.bias[0] = nullptr; opr.C[0] = sc->part0;
    opr.B[1] = Wo + (size_t)640 * N_STATE; opr.bias[1] = nullptr; opr.C[1] = sc->part1;
    opr.B[2] = nullptr; opr.bias[2] = nullptr; opr.C[2] = nullptr;
    gemm_tf32<<<gSpl, 128, GEMM_SMEM_BYTES>>>(sc->attn, opr,
        S_LEN, N_STATE, /*K=*/640, /*lda=*/N_STATE, /*aOffK=*/640, 0, 0);
    reduce_ln_kernel<<<S_LEN, 256>>>(sc->part0, sc->part1, bo, x,
                                     ln2g, ln2b, sc->x1, sc->h);

    // MLP1 (+exact GELU; output tf32-rounded)
    GemmBatch m1;
    m1.B[0] = W1; m1.bias[0] = b1; m1.C[0] = sc->h2;
    m1.B[1] = m1.B[2] = nullptr; m1.bias[1] = m1.bias[2] = nullptr;
    m1.C[1] = m1.C[2] = nullptr;
    gemm_tf32<<<gMLP1, 128, GEMM_SMEM_BYTES>>>(sc->h, m1,
        S_LEN, N_MLP, N_STATE, /*lda=*/N_STATE, /*aOffK=*/0, /*act=*/1, /*rnd=*/1);

    // MLP2 split-K x2 -> partials, then reduce (+bias +residual x1) -> out
    GemmBatch m2;
    m2.B[0] = W2;                          m2.bias[0] = nullptr; m2.C[0] = sc->part0;
    m2.B[1] = W2 + (size_t)2560 * N_STATE; m2.bias[1] = nullptr; m2.C[1] = sc->part1;
    m2.B[2] = nullptr; m2.bias[2] = nullptr; m2.C[2] = nullptr;
    gemm_tf32<<<gSpl, 128, GEMM_SMEM_BYTES>>>(sc->h2, m2,
        S_LEN, N_STATE, /*K=*/2560, /*lda=*/N_MLP, /*aOffK=*/2560, 0, 0);
    splitk_reduce<<<red_grid, 256>>>(sc->part0, sc->part1, b2, sc->x1, out);
}

// round 15
// speedup vs baseline: 1.0600x; 1.0600x over previous
#include <cuda_runtime.h>
#include <cuda_bf16.h>
#include <cstdint>
#include <cstddef>

// ---------------------------------------------------------------------------
// Problem constants
// ---------------------------------------------------------------------------
#define S_LEN   1500
#define N_STATE 1280
#define N_HEAD  20
#define D_HEAD  64
#define N_MLP   5120
#define NKT     24          // key tiles of 64

// ---------------------------------------------------------------------------
// Scratch (static device memory; no allocations anywhere)
// ---------------------------------------------------------------------------
struct Scratch {
    float h    [S_LEN * N_STATE];
    float q    [S_LEN * N_STATE];
    float k    [S_LEN * N_STATE];
    float v    [S_LEN * N_STATE];
    float attn [S_LEN * N_STATE];
    float x1   [S_LEN * N_STATE];
    float h2   [S_LEN * N_MLP];
    float part0[S_LEN * N_STATE];
    float part1[S_LEN * N_STATE];
};
__device__ Scratch g_scratch;

// ---------------------------------------------------------------------------
// Helpers
// ---------------------------------------------------------------------------
__device__ __forceinline__ uint32_t f2tf(float x) {
    uint32_t r;
    asm("cvt.rna.tf32.f32 %0, %1;" : "=r"(r) : "f"(x));
    return r;
}
__device__ __forceinline__ float rnd_tf(float x) {
    return __uint_as_float(f2tf(x));
}

// D = A(16x8, tf32, row) * B(8x8, tf32, col) + C, fp32 accum. In-place on acc.
__device__ __forceinline__ void mma_tf32(float acc[4], const uint32_t a[4], const uint32_t b[2]) {
    asm volatile(
        "mma.sync.aligned.m16n8k8.row.col.f32.tf32.tf32.f32 "
        "{%0,%1,%2,%3}, {%4,%5,%6,%7}, {%8,%9}, {%0,%1,%2,%3};\n"
        : "+f"(acc[0]), "+f"(acc[1]), "+f"(acc[2]), "+f"(acc[3])
        : "r"(a[0]), "r"(a[1]), "r"(a[2]), "r"(a[3]),
          "r"(b[0]), "r"(b[1]));
}

__device__ __forceinline__ void cp16(uint32_t dst, const float* src, bool ok) {
    int n = ok ? 16 : 0;   // zfill when out of range
    asm volatile("cp.async.cg.shared.global [%0], [%1], 16, %2;\n"
                 :: "r"(dst), "l"(src), "r"(n));
}
#define CP_COMMIT() asm volatile("cp.async.commit_group;\n")
#define CP_WAIT(N)  asm volatile("cp.async.wait_group %0;\n" :: "n"(N))

__device__ __forceinline__ float gelu_exact(float x) {
    return 0.5f * x * (1.0f + erff(x * 0.7071067811865475f));
}

// ---------------------------------------------------------------------------
// LayerNorm: one block per row, 256 threads, C = 1280 = 5*256.
// Output rounded to tf32 (RNA) — consumed only as GEMM A operand.
// ---------------------------------------------------------------------------
__global__ void ln_kernel(const float* __restrict__ x,
                          const float* __restrict__ gamma,
                          const float* __restrict__ beta,
                          float* __restrict__ out) {
    int row = blockIdx.x;
    int tid = threadIdx.x;
    const float* xr = x + (size_t)row * N_STATE;
    float* orow = out + (size_t)row * N_STATE;

    __shared__ float red[256];
    float local[5];
    float s = 0.f;
#pragma unroll
    for (int i = 0; i < 5; i++) { local[i] = xr[tid + i * 256]; s += local[i]; }
    red[tid] = s; __syncthreads();
#pragma unroll
    for (int o = 128; o > 0; o >>= 1) {
        if (tid < o) red[tid] += red[tid + o];
        __syncthreads();
    }
    float mu = red[0] * (1.0f / N_STATE);
    __syncthreads();

    float vs = 0.f;
#pragma unroll
    for (int i = 0; i < 5; i++) { float d = local[i] - mu; vs += d * d; }
    red[tid] = vs; __syncthreads();
#pragma unroll
    for (int o = 128; o > 0; o >>= 1) {
        if (tid < o) red[tid] += red[tid + o];
        __syncthreads();
    }
    float inv = rsqrtf(red[0] * (1.0f / N_STATE) + 1e-5f);

#pragma unroll
    for (int i = 0; i < 5; i++) {
        int c = tid + i * 256;
        orow[c] = rnd_tf((local[i] - mu) * inv * gamma[c] + beta[c]);
    }
}

// ---------------------------------------------------------------------------
// Fused split-K reduce + LayerNorm (one row per block):
//   x1 = p0 + p1 + bias + res            (written out: residual for later)
//   h  = rnd_tf(LN(x1) * gamma + beta)   (written out: next GEMM's A operand)
// ---------------------------------------------------------------------------
__global__ void reduce_ln_kernel(const float* __restrict__ p0,
                                 const float* __restrict__ p1,
                                 const float* __restrict__ bias,
                                 const float* __restrict__ res,
                                 const float* __restrict__ gamma,
                                 const float* __restrict__ beta,
                                 float* __restrict__ x1,
                                 float* __restrict__ h) {
    int row = blockIdx.x;
    int tid = threadIdx.x;
    size_t off = (size_t)row * N_STATE;

    __shared__ float red[256];
    float local[5];
    float s = 0.f;
#pragma unroll
    for (int i = 0; i < 5; i++) {
        int c = tid + i * 256;
        float v = p0[off + c] + p1[off + c] + bias[c] + res[off + c];
        x1[off + c] = v;
        local[i] = v;
        s += v;
    }
    red[tid] = s; __syncthreads();
#pragma unroll
    for (int o = 128; o > 0; o >>= 1) {
        if (tid < o) red[tid] += red[tid + o];
        __syncthreads();
    }
    float mu = red[0] * (1.0f / N_STATE);
    __syncthreads();

    float vs = 0.f;
#pragma unroll
    for (int i = 0; i < 5; i++) { float d = local[i] - mu; vs += d * d; }
    red[tid] = vs; __syncthreads();
#pragma unroll
    for (int o = 128; o > 0; o >>= 1) {
        if (tid < o) red[tid] += red[tid + o];
        __syncthreads();
    }
    float inv = rsqrtf(red[0] * (1.0f / N_STATE) + 1e-5f);

#pragma unroll
    for (int i = 0; i < 5; i++) {
        int c = tid + i * 256;
        h[off + c] = rnd_tf((local[i] - mu) * inv * gamma[c] + beta[c]);
    }
}

// ---------------------------------------------------------------------------
// tf32 MMA GEMM, templated on <BN, NSTG>, batched over blockIdx.z:
//   batch mode (aOffK=0): C_z = act(A @ B_z + bias_z), z = different weights
//   split-K mode (aOffK>0): C_z = A[:, z*aOffK:(z+1)*aOffK] @ B_z (partials)
// BM=128, BK=32; 256 threads = 8 warps (2m x 4n), warp tile 64 x (BN/4).
// R9-proven inner loop (scalar LDS A-frags, in-loop RNA CVT B-frags).
//   BN=128, 3 stages: the measured-best config (tensor 37.8%, 46 us/launch).
//   BN=160, 2 stages: QKV-only — grid 8x12x3 = 288 <= 296 slots -> ONE wave
//     (vs 360 CTAs / 1.5 waves at BN=128). BS_STRIDE 168 ≡ 8 (mod 32): banks
//     (8t+g) conflict-free, same pattern as 136.
// ONE __syncthreads per 32-deep k-slab in both stage modes.
// ---------------------------------------------------------------------------
#define G_BM 128
#define G_BK 32
#define AS_STRIDE 36
#define AS_BUF (G_BM * AS_STRIDE)                      // 4608 words

struct GemmBatch {
    const float* B[3];
    const float* bias[3];
    float*       C[3];
};

template<int BN, int NSTG>
__global__ __launch_bounds__(256, 2)
void gemm_tf32(const float* __restrict__ A, GemmBatch args,
               int M, int N, int K, int lda, int aOffK, int act, int rnd) {
    constexpr int BS_STRIDE = BN + 8;
    constexpr int BS_BUF    = G_BK * BS_STRIDE;
    constexpr int STAGE_W   = AS_BUF + BS_BUF;
    constexpr int NJ        = BN / 32;     // j-subtiles per warp (n = NJ*8)
    constexpr int WNT       = BN / 4;      // warp n-tile

    extern __shared__ uint32_t sm[];

    int z = blockIdx.z;
    const float* __restrict__ Bp   = args.B[z];
    const float* __restrict__ bias = args.bias[z];
    float* __restrict__       C    = args.C[z];

    int tid  = threadIdx.x;
    int warp = tid >> 5, lane = tid & 31;
    int g = lane >> 2, t = lane & 3;
    int wm = warp >> 2;       // 0..1 -> rows wm*64
    int wn = warp & 3;        // 0..3 -> cols wn*WNT
    int bm0 = blockIdx.y * G_BM;
    int bn0 = blockIdx.x * BN;

    uint32_t sbase = (uint32_t)__cvta_generic_to_shared(sm);

    // cp.async mappings
    int larow = tid >> 3;          // 0..31 (+32*i)
    int lacol = (tid & 7) * 4;     // k offset

    const float* aptr = A + (size_t)(bm0 + larow) * lda + (size_t)z * aOffK + lacol;

    auto loadg = [&](int k0, int stg) {
        uint32_t ad = sbase + (stg * STAGE_W) * 4;
#pragma unroll
        for (int i = 0; i < 4; i++) {
            int r = bm0 + larow + 32 * i;
            cp16(ad + ((larow + 32 * i) * AS_STRIDE + lacol) * 4,
                 aptr + (size_t)(32 * i) * lda + k0, r < M);
        }
        uint32_t bd = ad + AS_BUF * 4;
#pragma unroll
        for (int i = 0; i < BN / 32; i++) {
            int idx = i * 256 + tid;           // over 32 * BN/4 float4s
            int br  = idx / (BN / 4);
            int bc  = (idx % (BN / 4)) * 4;
            cp16(bd + (br * BS_STRIDE + bc) * 4,
                 Bp + (size_t)(k0 + br) * N + bn0 + bc, true);
        }
        CP_COMMIT();
    };

    float acc[4][NJ][4];
#pragma unroll
    for (int i = 0; i < 4; i++)
#pragma unroll
        for (int j = 0; j < NJ; j++)
#pragma unroll
            for (int r = 0; r < 4; r++) acc[i][j][r] = 0.f;

    int nk = K / G_BK;
    loadg(0, 0);
    if (NSTG == 3 && nk > 1) loadg(G_BK, 1);

    int stg = 0;
    for (int kt = 0; kt < nk; kt++) {
        if (NSTG == 3 && kt + 1 < nk) { CP_WAIT(1); }
        else                          { CP_WAIT(0); }
        __syncthreads();   // stage kt ready; all warps done with old stage
        if (NSTG == 3) {
            if (kt + 2 < nk) {
                int ns = stg + 2; if (ns >= 3) ns -= 3;
                loadg((kt + 2) * G_BK, ns);
            }
        } else {
            if (kt + 1 < nk) loadg((kt + 1) * G_BK, stg ^ 1);
        }

        const uint32_t* ab = sm + stg * STAGE_W;
        const uint32_t* bb = ab + AS_BUF;
#pragma unroll
        for (int ks = 0; ks < 4; ks++) {
            uint32_t af[4][4], bf[NJ][2];
#pragma unroll
            for (int i = 0; i < 4; i++) {
                const uint32_t* base = ab + (wm * 64 + i * 16 + g) * AS_STRIDE + ks * 8 + t;
                af[i][0] = base[0];
                af[i][1] = base[8 * AS_STRIDE];
                af[i][2] = base[4];
                af[i][3] = base[8 * AS_STRIDE + 4];
            }
#pragma unroll
            for (int j = 0; j < NJ; j++) {
                const uint32_t* base = bb + (ks * 8 + t) * BS_STRIDE + wn * WNT + j * 8 + g;
                bf[j][0] = f2tf(__uint_as_float(base[0]));
                bf[j][1] = f2tf(__uint_as_float(base[4 * BS_STRIDE]));
            }
#pragma unroll
            for (int i = 0; i < 4; i++)
#pragma unroll
                for (int j = 0; j < NJ; j++)
                    mma_tf32(acc[i][j], af[i], bf[j]);
        }
        if (++stg == NSTG) stg = 0;
    }

    // epilogue
#pragma unroll
    for (int i = 0; i < 4; i++) {
        int r0 = bm0 + wm * 64 + i * 16 + g;
        int r1 = r0 + 8;
#pragma unroll
        for (int j = 0; j < NJ; j++) {
            int c = bn0 + wn * WNT + j * 8 + 2 * t;
            float bb0 = bias ? bias[c]     : 0.f;
            float bb1 = bias ? bias[c + 1] : 0.f;
            if (r0 < M) {
                float v0 = acc[i][j][0] + bb0, v1 = acc[i][j][1] + bb1;
                if (act) { v0 = gelu_exact(v0); v1 = gelu_exact(v1); }
                if (rnd) { v0 = rnd_tf(v0); v1 = rnd_tf(v1); }
                *(float2*)&C[(size_t)r0 * N + c] = make_float2(v0, v1);
            }
            if (r1 < M) {
                float v2 = acc[i][j][2] + bb0, v3 = acc[i][j][3] + bb1;
                if (act) { v2 = gelu_exact(v2); v3 = gelu_exact(v3); }
                if (rnd) { v2 = rnd_tf(v2); v3 = rnd_tf(v3); }
                *(float2*)&C[(size_t)r1 * N + c] = make_float2(v2, v3);
            }
        }
    }
}

#define GEMM128_SMEM (3 * (AS_BUF + G_BK * 136) * 4)   // 107520
#define GEMM160_SMEM (2 * (AS_BUF + G_BK * 168) * 4)   // 79872

// ---------------------------------------------------------------------------
// Split-K reduce: out = p0 + p1 + bias + res   (N = N_STATE columns)
// ---------------------------------------------------------------------------
__global__ void splitk_reduce(const float* __restrict__ p0,
                              const float* __restrict__ p1,
                              const float* __restrict__ bias,
                              const float* __restrict__ res,
                              float* __restrict__ out) {
    int i = blockIdx.x * blockDim.x + threadIdx.x;           // float4 index
    const int total4 = S_LEN * N_STATE / 4;
    if (i >= total4) return;
    float4 a = ((const float4*)p0)[i];
    float4 b = ((const float4*)p1)[i];
    float4 r = ((const float4*)res)[i];
    int c = (i * 4) % N_STATE;
    float4 bb = *(const float4*)&bias[c];
    float4 o;
    o.x = a.x + b.x + bb.x + r.x;
    o.y = a.y + b.y + bb.y + r.y;
    o.z = a.z + b.z + bb.z + r.z;
    o.w = a.w + b.w + bb.w + r.w;
    ((float4*)out)[i] = o;
}

// ---------------------------------------------------------------------------
// Fused flash attention (non-causal), k-dim permutation trick. (unchanged)
// Block = (q-tile of 128, head), 256 threads = 8 warps, warp owns 16 q rows.
//  * QK^T: Q frags load dims (2t, 2t+1); K B-frags = one LDS.64 whose halves
//    land directly in bf[0]/bf[1] (operand order -> no repack).
//  * P.V : S/P C-fragment IS the PV A-fragment (P never touches smem).
// Double-buffered K/V via cp.async; one __syncthreads per tile.
// smem = 2*64*72 + 2*64*68 words = 71680 B -> 2 CTAs/SM.
// ---------------------------------------------------------------------------
#define KB_STRIDE 72
#define VB_STRIDE 68
#define KBUF_W (64 * KB_STRIDE)               // 4608
#define VBUF_W (64 * VB_STRIDE)               // 4352
#define ATTN_SMEM_BYTES ((2 * KBUF_W + 2 * VBUF_W) * 4)   // 71680

__global__ __launch_bounds__(256, 2)
void attn_kernel(const float* __restrict__ qp, const float* __restrict__ kp,
                 const float* __restrict__ vp, float* __restrict__ out) {
    extern __shared__ uint32_t smn[];

    int qt = blockIdx.x;
    int h  = blockIdx.y;
    int tid = threadIdx.x, warp = tid >> 5, lane = tid & 31;
    int g = lane >> 2, t = lane & 3;
    int qrow0 = qt * 128 + warp * 16;
    uint32_t sbase = (uint32_t)__cvta_generic_to_shared(smn);

    // ---- preload Q fragments with permuted k: word0<->dim 2t, word2<->2t+1 ----
    uint32_t qf[8][4];
    {
        int rA = qrow0 + g, rB = qrow0 + g + 8;
        bool okA = rA < S_LEN, okB = rB < S_LEN;
        const float* qA = qp + (size_t)rA * N_STATE + h * D_HEAD;
        const float* qB = qp + (size_t)rB * N_STATE + h * D_HEAD;
#pragma unroll
        for (int ks = 0; ks < 8; ks++) {
            int d0 = ks * 8 + 2 * t;
            float a0 = okA ? qA[d0]     : 0.f;
            float a1 = okB ? qB[d0]     : 0.f;
            float a2 = okA ? qA[d0 + 1] : 0.f;
            float a3 = okB ? qB[d0 + 1] : 0.f;
            qf[ks][0] = __float_as_uint(a0 * 0.125f);
            qf[ks][1] = __float_as_uint(a1 * 0.125f);
            qf[ks][2] = __float_as_uint(a2 * 0.125f);
            qf[ks][3] = __float_as_uint(a3 * 0.125f);
        }
    }

    float of[8][4];
#pragma unroll
    for (int j = 0; j < 8; j++)
#pragma unroll
        for (int r = 0; r < 4; r++) of[j][r] = 0.f;
    float m0 = -1e30f, m1 = -1e30f, l0 = 0.f, l1 = 0.f;

    int lrow = tid >> 4;            // 0..15
    int lc4  = (tid & 15) * 4;      // 0..60
    const float* kpb = kp + h * D_HEAD + lc4;
    const float* vpb = vp + h * D_HEAD + lc4;

    auto issue = [&](int kt, int buf) {
#pragma unroll
        for (int p = 0; p < 4; p++) {
            int row = lrow + p * 16;
            int gk = kt * 64 + row;
            cp16(sbase + (buf * KBUF_W + row * KB_STRIDE + lc4) * 4,
                 kpb + (size_t)gk * N_STATE, gk < S_LEN);
        }
#pragma unroll
        for (int p = 0; p < 4; p++) {
            int row = lrow + p * 16;
            int gk = kt * 64 + row;
            cp16(sbase + (2 * KBUF_W + buf * VBUF_W + row * VB_STRIDE + lc4) * 4,
                 vpb + (size_t)gk * N_STATE, gk < S_LEN);
        }
        CP_COMMIT();
    };

    issue(0, 0);

    for (int kt = 0; kt < NKT; kt++) {
        int buf = kt & 1;
        CP_WAIT(0);          // current tile resident
        __syncthreads();     // all warps done with previous tile's buffers
        if (kt + 1 < NKT) issue(kt + 1, buf ^ 1);   // prefetch overlaps compute

        const uint32_t* Kb = smn + buf * KBUF_W;
        const uint32_t* Vb = smn + 2 * KBUF_W + buf * VBUF_W;

        // ---- S = Q * K^T  (16 x 64 per warp); B-frag = one LDS.64 ----
        float sacc[8][4];
#pragma unroll
        for (int j = 0; j < 8; j++)
#pragma unroll
            for (int r = 0; r < 4; r++) sacc[j][r] = 0.f;

#pragma unroll
        for (int ks = 0; ks < 8; ks++) {
#pragma unroll
            for (int j = 0; j < 8; j++) {
                uint2 kb = *(const uint2*)&Kb[(j * 8 + g) * KB_STRIDE + ks * 8 + 2 * t];
                uint32_t bf[2] = {kb.x, kb.y};
                mma_tf32(sacc[j], qf[ks], bf);
            }
        }

        // ---- mask padded keys (only last tile) ----
        if (kt == NKT - 1) {
#pragma unroll
            for (int j = 0; j < 8; j++) {
                int c = j * 8 + 2 * t;
                if (1472 + c     >= S_LEN) { sacc[j][0] = -1e30f; sacc[j][2] = -1e30f; }
                if (1472 + c + 1 >= S_LEN) { sacc[j][1] = -1e30f; sacc[j][3] = -1e30f; }
            }
        }

        // ---- online softmax ----
        float tm0 = -1e30f, tm1 = -1e30f;
#pragma unroll
        for (int j = 0; j < 8; j++) {
            tm0 = fmaxf(tm0, fmaxf(sacc[j][0], sacc[j][1]));
            tm1 = fmaxf(tm1, fmaxf(sacc[j][2], sacc[j][3]));
        }
        tm0 = fmaxf(tm0, __shfl_xor_sync(0xffffffffu, tm0, 1));
        tm0 = fmaxf(tm0, __shfl_xor_sync(0xffffffffu, tm0, 2));
        tm1 = fmaxf(tm1, __shfl_xor_sync(0xffffffffu, tm1, 1));
        tm1 = fmaxf(tm1, __shfl_xor_sync(0xffffffffu, tm1, 2));

        float nm0 = fmaxf(m0, tm0), nm1 = fmaxf(m1, tm1);
        float c0 = __expf(m0 - nm0), c1 = __expf(m1 - nm1);
        l0 *= c0; l1 *= c1;
#pragma unroll
        for (int j = 0; j < 8; j++) {
            of[j][0] *= c0; of[j][1] *= c0;
            of[j][2] *= c1; of[j][3] *= c1;
        }
        m0 = nm0; m1 = nm1;

        // ---- P = exp(S - m), tf32-rounded, kept in the sacc registers ----
        float ps0 = 0.f, ps1 = 0.f;
#pragma unroll
        for (int j = 0; j < 8; j++) {
            float p0 = rnd_tf(__expf(sacc[j][0] - nm0));
            float p1 = rnd_tf(__expf(sacc[j][1] - nm0));
            float p2 = rnd_tf(__expf(sacc[j][2] - nm1));
            float p3 = rnd_tf(__expf(sacc[j][3] - nm1));
            sacc[j][0] = p0; sacc[j][1] = p1; sacc[j][2] = p2; sacc[j][3] = p3;
            ps0 += p0 + p1; ps1 += p2 + p3;
        }
        ps0 += __shfl_xor_sync(0xffffffffu, ps0, 1);
        ps0 += __shfl_xor_sync(0xffffffffu, ps0, 2);
        ps1 += __shfl_xor_sync(0xffffffffu, ps1, 1);
        ps1 += __shfl_xor_sync(0xffffffffu, ps1, 2);
        l0 += ps0; l1 += ps1;

        // ---- O += P * V : A-fragment comes straight from sacc registers ----
#pragma unroll
        for (int ksJ = 0; ksJ < 8; ksJ++) {     // key block = S column block
            uint32_t af[4];
            af[0] = __float_as_uint(sacc[ksJ][0]);   // P[g   ][key 2t]
            af[1] = __float_as_uint(sacc[ksJ][2]);   // P[g+8 ][key 2t]
            af[2] = __float_as_uint(sacc[ksJ][1]);   // P[g   ][key 2t+1]
            af[3] = __float_as_uint(sacc[ksJ][3]);   // P[g+8 ][key 2t+1]
            const uint32_t* vrow = Vb + (ksJ * 8 + 2 * t) * VB_STRIDE + g;
#pragma unroll
            for (int j = 0; j < 8; j++) {
                uint32_t bf[2];
                bf[0] = vrow[j * 8];                 // V[key 2t  ][dim j8+g]
                bf[1] = vrow[VB_STRIDE + j * 8];     // V[key 2t+1][dim j8+g]
                mma_tf32(of[j], af, bf);
            }
        }
    }

    // ---- finalize + store (rounded: feeds O-proj as A operand) ----
    float inv0 = 1.0f / l0, inv1 = 1.0f / l1;
    int r0 = qrow0 + g, r1 = qrow0 + g + 8;
#pragma unroll
    for (int j = 0; j < 8; j++) {
        int c = h * D_HEAD + j * 8 + 2 * t;
        if (r0 < S_LEN)
            *(float2*)&out[(size_t)r0 * N_STATE + c] =
                make_float2(rnd_tf(of[j][0] * inv0), rnd_tf(of[j][1] * inv0));
        if (r1 < S_LEN)
            *(float2*)&out[(size_t)r1 * N_STATE + c] =
                make_float2(rnd_tf(of[j][2] * inv1), rnd_tf(of[j][3] * inv1));
    }
}

// ---------------------------------------------------------------------------
// Launch: 8 kernels on the default stream (graph-capturable, alloc-free)
// ---------------------------------------------------------------------------
extern "C" void kernel_launch(void* const* d_in, const int* in_sizes, int n_in,
                              void* d_out, int out_size) {
    (void)in_sizes; (void)n_in; (void)out_size;

    const float* x    = (const float*)d_in[0];
    const float* Wq   = (const float*)d_in[1];
    const float* bq   = (const float*)d_in[2];
    const float* Wk   = (const float*)d_in[3];
    const float* Wv   = (const float*)d_in[4];
    const float* bv   = (const float*)d_in[5];
    const float* Wo   = (const float*)d_in[6];
    const float* bo   = (const float*)d_in[7];
    const float* ln1g = (const float*)d_in[8];
    const float* ln1b = (const float*)d_in[9];
    const float* ln2g = (const float*)d_in[10];
    const float* ln2b = (const float*)d_in[11];
    const float* W1   = (const float*)d_in[12];
    const float* b1   = (const float*)d_in[13];
    const float* W2   = (const float*)d_in[14];
    const float* b2   = (const float*)d_in[15];
    float* out = (float*)d_out;

    Scratch* sc = nullptr;
    cudaGetSymbolAddress((void**)&sc, g_scratch);

    cudaFuncSetAttribute(gemm_tf32<128, 3>,
                         cudaFuncAttributeMaxDynamicSharedMemorySize,
                         GEMM128_SMEM);
    cudaFuncSetAttribute(gemm_tf32<160, 2>,
                         cudaFuncAttributeMaxDynamicSharedMemorySize,
                         GEMM160_SMEM);
    cudaFuncSetAttribute(attn_kernel,
                         cudaFuncAttributeMaxDynamicSharedMemorySize,
                         ATTN_SMEM_BYTES);

    dim3 gQKV (N_STATE / 160, (S_LEN + G_BM - 1) / G_BM, 3);   // (8,12,3)=288
    dim3 gSpl (N_STATE / 128, (S_LEN + G_BM - 1) / G_BM, 2);   // (10,12,2)=240
    dim3 gMLP1(N_MLP  / 128, (S_LEN + G_BM - 1) / G_BM, 1);    // (40,12,1)=480
    const int red_grid = (S_LEN * N_STATE / 4 + 255) / 256;

    // LN1 (output tf32-rounded)
    ln_kernel<<<S_LEN, 256>>>(x, ln1g, ln1b, sc->h);

    // QKV projections: BN=160 -> 288 CTAs = ONE wave at 2 CTAs/SM
    GemmBatch qkv;
    qkv.B[0] = Wq; qkv.bias[0] = bq;      qkv.C[0] = sc->q;
    qkv.B[1] = Wk; qkv.bias[1] = nullptr; qkv.C[1] = sc->k;
    qkv.B[2] = Wv; qkv.bias[2] = bv;      qkv.C[2] = sc->v;
    gemm_tf32<160, 2><<<gQKV, 256, GEMM160_SMEM>>>(sc->h, qkv,
        S_LEN, N_STATE, N_STATE, /*lda=*/N_STATE, /*aOffK=*/0, 0, /*rnd=*/1);

    // attention (output tf32-rounded)
    attn_kernel<<<dim3(12, N_HEAD), 256, ATTN_SMEM_BYTES>>>(sc->q, sc->k, sc->v, sc->attn);

    // O-proj split-K x2 -> partials, then fused reduce(+bias+residual)+LN2
    GemmBatch opr;
    opr.B[0] = Wo;                         opr.bias[0] = nullptr; opr.C[0] = sc->part0;
    opr.B[1] = Wo + (size_t)640 * N_STATE; opr.bias[1] = nullptr; opr.C[1] = sc->part1;
    opr.B[2] = nullptr; opr.bias[2] = nullptr; opr.C[2] = nullptr;
    gemm_tf32<128, 3><<<gSpl, 256, GEMM128_SMEM>>>(sc->attn, opr,
        S_LEN, N_STATE, /*K=*/640, /*lda=*/N_STATE, /*aOffK=*/640, 0, 0);
    reduce_ln_kernel<<<S_LEN, 256>>>(sc->part0, sc->part1, bo, x,
                                     ln2g, ln2b, sc->x1, sc->h);

    // MLP1 (+exact GELU; output tf32-rounded)
    GemmBatch m1;
    m1.B[0] = W1; m1.bias[0] = b1; m1.C[0] = sc->h2;
    m1.B[1] = m1.B[2] = nullptr; m1.bias[1] = m1.bias[2] = nullptr;
    m1.C[1] = m1.C[2] = nullptr;
    gemm_tf32<128, 3><<<gMLP1, 256, GEMM128_SMEM>>>(sc->h, m1,
        S_LEN, N_MLP, N_STATE, /*lda=*/N_STATE, /*aOffK=*/0, /*act=*/1, /*rnd=*/1);

    // MLP2 split-K x2 -> partials, then reduce (+bias +residual x1) -> out
    GemmBatch m2;
    m2.B[0] = W2;                          m2.bias[0] = nullptr; m2.C[0] = sc->part0;
    m2.B[1] = W2 + (size_t)2560 * N_STATE; m2.bias[1] = nullptr; m2.C[1] = sc->part1;
    m2.B[2] = nullptr; m2.bias[2] = nullptr; m2.C[2] = nullptr;
    gemm_tf32<128, 3><<<gSpl, 256, GEMM128_SMEM>>>(sc->h2, m2,
        S_LEN, N_STATE, /*K=*/2560, /*lda=*/N_MLP, /*aOffK=*/2560, 0, 0);
    splitk_reduce<<<red_grid, 256>>>(sc->part0, sc->part1, b2, sc->x1, out);
}

// round 17
// speedup vs baseline: 1.0730x; 1.0122x over previous
#include <cuda_runtime.h>
#include <cuda_bf16.h>
#include <cstdint>
#include <cstddef>

// ---------------------------------------------------------------------------
// Problem constants
// ---------------------------------------------------------------------------
#define S_LEN   1500
#define N_STATE 1280
#define N_HEAD  20
#define D_HEAD  64
#define N_MLP   5120
#define NKT     24          // key tiles of 64

// ---------------------------------------------------------------------------
// Scratch (static device memory; no allocations anywhere)
// ---------------------------------------------------------------------------
struct Scratch {
    float h    [S_LEN * N_STATE];
    float q    [S_LEN * N_STATE];
    float k    [S_LEN * N_STATE];
    float v    [S_LEN * N_STATE];
    float attn [S_LEN * N_STATE];
    float x1   [S_LEN * N_STATE];
    float h2   [S_LEN * N_MLP];
    float part0[S_LEN * N_STATE];
    float part1[S_LEN * N_STATE];
};
__device__ Scratch g_scratch;

// ---------------------------------------------------------------------------
// Helpers
// ---------------------------------------------------------------------------
__device__ __forceinline__ uint32_t f2tf(float x) {
    uint32_t r;
    asm("cvt.rna.tf32.f32 %0, %1;" : "=r"(r) : "f"(x));
    return r;
}
__device__ __forceinline__ float rnd_tf(float x) {
    return __uint_as_float(f2tf(x));
}

// D = A(16x8, tf32, row) * B(8x8, tf32, col) + C, fp32 accum. In-place on acc.
__device__ __forceinline__ void mma_tf32(float acc[4], const uint32_t a[4], const uint32_t b[2]) {
    asm volatile(
        "mma.sync.aligned.m16n8k8.row.col.f32.tf32.tf32.f32 "
        "{%0,%1,%2,%3}, {%4,%5,%6,%7}, {%8,%9}, {%0,%1,%2,%3};\n"
        : "+f"(acc[0]), "+f"(acc[1]), "+f"(acc[2]), "+f"(acc[3])
        : "r"(a[0]), "r"(a[1]), "r"(a[2]), "r"(a[3]),
          "r"(b[0]), "r"(b[1]));
}

__device__ __forceinline__ void cp16(uint32_t dst, const float* src, bool ok) {
    int n = ok ? 16 : 0;   // zfill when out of range
    asm volatile("cp.async.cg.shared.global [%0], [%1], 16, %2;\n"
                 :: "r"(dst), "l"(src), "r"(n));
}
#define CP_COMMIT() asm volatile("cp.async.commit_group;\n")
#define CP_WAIT(N)  asm volatile("cp.async.wait_group %0;\n" :: "n"(N))

__device__ __forceinline__ float gelu_exact(float x) {
    return 0.5f * x * (1.0f + erff(x * 0.7071067811865475f));
}

// ---------------------------------------------------------------------------
// LayerNorm: one block per row, 256 threads, C = 1280 = 5*256.
// Output rounded to tf32 (RNA) — consumed only as GEMM A operand.
// ---------------------------------------------------------------------------
__global__ void ln_kernel(const float* __restrict__ x,
                          const float* __restrict__ gamma,
                          const float* __restrict__ beta,
                          float* __restrict__ out) {
    int row = blockIdx.x;
    int tid = threadIdx.x;
    const float* xr = x + (size_t)row * N_STATE;
    float* orow = out + (size_t)row * N_STATE;

    __shared__ float red[256];
    float local[5];
    float s = 0.f;
#pragma unroll
    for (int i = 0; i < 5; i++) { local[i] = xr[tid + i * 256]; s += local[i]; }
    red[tid] = s; __syncthreads();
#pragma unroll
    for (int o = 128; o > 0; o >>= 1) {
        if (tid < o) red[tid] += red[tid + o];
        __syncthreads();
    }
    float mu = red[0] * (1.0f / N_STATE);
    __syncthreads();

    float vs = 0.f;
#pragma unroll
    for (int i = 0; i < 5; i++) { float d = local[i] - mu; vs += d * d; }
    red[tid] = vs; __syncthreads();
#pragma unroll
    for (int o = 128; o > 0; o >>= 1) {
        if (tid < o) red[tid] += red[tid + o];
        __syncthreads();
    }
    float inv = rsqrtf(red[0] * (1.0f / N_STATE) + 1e-5f);

#pragma unroll
    for (int i = 0; i < 5; i++) {
        int c = tid + i * 256;
        orow[c] = rnd_tf((local[i] - mu) * inv * gamma[c] + beta[c]);
    }
}

// ---------------------------------------------------------------------------
// Fused split-K reduce + LayerNorm (one row per block):
//   x1 = p0 + p1 + bias + res            (written out: residual for later)
//   h  = rnd_tf(LN(x1) * gamma + beta)   (written out: next GEMM's A operand)
// ---------------------------------------------------------------------------
__global__ void reduce_ln_kernel(const float* __restrict__ p0,
                                 const float* __restrict__ p1,
                                 const float* __restrict__ bias,
                                 const float* __restrict__ res,
                                 const float* __restrict__ gamma,
                                 const float* __restrict__ beta,
                                 float* __restrict__ x1,
                                 float* __restrict__ h) {
    int row = blockIdx.x;
    int tid = threadIdx.x;
    size_t off = (size_t)row * N_STATE;

    __shared__ float red[256];
    float local[5];
    float s = 0.f;
#pragma unroll
    for (int i = 0; i < 5; i++) {
        int c = tid + i * 256;
        float v = p0[off + c] + p1[off + c] + bias[c] + res[off + c];
        x1[off + c] = v;
        local[i] = v;
        s += v;
    }
    red[tid] = s; __syncthreads();
#pragma unroll
    for (int o = 128; o > 0; o >>= 1) {
        if (tid < o) red[tid] += red[tid + o];
        __syncthreads();
    }
    float mu = red[0] * (1.0f / N_STATE);
    __syncthreads();

    float vs = 0.f;
#pragma unroll
    for (int i = 0; i < 5; i++) { float d = local[i] - mu; vs += d * d; }
    red[tid] = vs; __syncthreads();
#pragma unroll
    for (int o = 128; o > 0; o >>= 1) {
        if (tid < o) red[tid] += red[tid + o];
        __syncthreads();
    }
    float inv = rsqrtf(red[0] * (1.0f / N_STATE) + 1e-5f);

#pragma unroll
    for (int i = 0; i < 5; i++) {
        int c = tid + i * 256;
        h[off + c] = rnd_tf((local[i] - mu) * inv * gamma[c] + beta[c]);
    }
}

// ---------------------------------------------------------------------------
// tf32 MMA GEMM, templated on <BN, NSTG>, batched over blockIdx.z:
//   batch mode (aOffK=0): C_z = act(A @ B_z + bias_z), z = different weights
//   split-K mode (aOffK>0): C_z = A[:, z*aOffK:(z+1)*aOffK] @ B_z (partials)
// BM=128, BK=32; 256 threads = 8 warps (2m x 4n), warp tile 64 x (BN/4).
// R9-proven inner loop (scalar LDS A-frags, in-loop RNA CVT B-frags).
//   BN=128, 3 stages: measured-best for long-K split launches.
//   BN=160, 2 stages: QKV (288 CTAs = 1 wave) and MLP1 (384 CTAs = 1.30
//     waves vs 1.62 at BN=128); slabs are latency-bound so the 1.25x larger
//     slab is nearly free. BS_STRIDE 168 ≡ 8 (mod 32): banks (8t+g) free.
// ONE __syncthreads per 32-deep k-slab in both stage modes.
// ---------------------------------------------------------------------------
#define G_BM 128
#define G_BK 32
#define AS_STRIDE 36
#define AS_BUF (G_BM * AS_STRIDE)                      // 4608 words

struct GemmBatch {
    const float* B[3];
    const float* bias[3];
    float*       C[3];
};

template<int BN, int NSTG>
__global__ __launch_bounds__(256, 2)
void gemm_tf32(const float* __restrict__ A, GemmBatch args,
               int M, int N, int K, int lda, int aOffK, int act, int rnd) {
    constexpr int BS_STRIDE = BN + 8;
    constexpr int BS_BUF    = G_BK * BS_STRIDE;
    constexpr int STAGE_W   = AS_BUF + BS_BUF;
    constexpr int NJ        = BN / 32;     // j-subtiles per warp (n = NJ*8)
    constexpr int WNT       = BN / 4;      // warp n-tile

    extern __shared__ uint32_t sm[];

    int z = blockIdx.z;
    const float* __restrict__ Bp   = args.B[z];
    const float* __restrict__ bias = args.bias[z];
    float* __restrict__       C    = args.C[z];

    int tid  = threadIdx.x;
    int warp = tid >> 5, lane = tid & 31;
    int g = lane >> 2, t = lane & 3;
    int wm = warp >> 2;       // 0..1 -> rows wm*64
    int wn = warp & 3;        // 0..3 -> cols wn*WNT
    int bm0 = blockIdx.y * G_BM;
    int bn0 = blockIdx.x * BN;

    uint32_t sbase = (uint32_t)__cvta_generic_to_shared(sm);

    // cp.async mappings
    int larow = tid >> 3;          // 0..31 (+32*i)
    int lacol = (tid & 7) * 4;     // k offset

    const float* aptr = A + (size_t)(bm0 + larow) * lda + (size_t)z * aOffK + lacol;

    auto loadg = [&](int k0, int stg) {
        uint32_t ad = sbase + (stg * STAGE_W) * 4;
#pragma unroll
        for (int i = 0; i < 4; i++) {
            int r = bm0 + larow + 32 * i;
            cp16(ad + ((larow + 32 * i) * AS_STRIDE + lacol) * 4,
                 aptr + (size_t)(32 * i) * lda + k0, r < M);
        }
        uint32_t bd = ad + AS_BUF * 4;
#pragma unroll
        for (int i = 0; i < BN / 32; i++) {
            int idx = i * 256 + tid;           // over 32 * BN/4 float4s
            int br  = idx / (BN / 4);
            int bc  = (idx % (BN / 4)) * 4;
            cp16(bd + (br * BS_STRIDE + bc) * 4,
                 Bp + (size_t)(k0 + br) * N + bn0 + bc, true);
        }
        CP_COMMIT();
    };

    float acc[4][NJ][4];
#pragma unroll
    for (int i = 0; i < 4; i++)
#pragma unroll
        for (int j = 0; j < NJ; j++)
#pragma unroll
            for (int r = 0; r < 4; r++) acc[i][j][r] = 0.f;

    int nk = K / G_BK;
    loadg(0, 0);
    if (NSTG == 3 && nk > 1) loadg(G_BK, 1);

    int stg = 0;
    for (int kt = 0; kt < nk; kt++) {
        if (NSTG == 3 && kt + 1 < nk) { CP_WAIT(1); }
        else                          { CP_WAIT(0); }
        __syncthreads();   // stage kt ready; all warps done with old stage
        if (NSTG == 3) {
            if (kt + 2 < nk) {
                int ns = stg + 2; if (ns >= 3) ns -= 3;
                loadg((kt + 2) * G_BK, ns);
            }
        } else {
            if (kt + 1 < nk) loadg((kt + 1) * G_BK, stg ^ 1);
        }

        const uint32_t* ab = sm + stg * STAGE_W;
        const uint32_t* bb = ab + AS_BUF;
#pragma unroll
        for (int ks = 0; ks < 4; ks++) {
            uint32_t af[4][4], bf[NJ][2];
#pragma unroll
            for (int i = 0; i < 4; i++) {
                const uint32_t* base = ab + (wm * 64 + i * 16 + g) * AS_STRIDE + ks * 8 + t;
                af[i][0] = base[0];
                af[i][1] = base[8 * AS_STRIDE];
                af[i][2] = base[4];
                af[i][3] = base[8 * AS_STRIDE + 4];
            }
#pragma unroll
            for (int j = 0; j < NJ; j++) {
                const uint32_t* base = bb + (ks * 8 + t) * BS_STRIDE + wn * WNT + j * 8 + g;
                bf[j][0] = f2tf(__uint_as_float(base[0]));
                bf[j][1] = f2tf(__uint_as_float(base[4 * BS_STRIDE]));
            }
#pragma unroll
            for (int i = 0; i < 4; i++)
#pragma unroll
                for (int j = 0; j < NJ; j++)
                    mma_tf32(acc[i][j], af[i], bf[j]);
        }
        if (++stg == NSTG) stg = 0;
    }

    // epilogue
#pragma unroll
    for (int i = 0; i < 4; i++) {
        int r0 = bm0 + wm * 64 + i * 16 + g;
        int r1 = r0 + 8;
#pragma unroll
        for (int j = 0; j < NJ; j++) {
            int c = bn0 + wn * WNT + j * 8 + 2 * t;
            float bb0 = bias ? bias[c]     : 0.f;
            float bb1 = bias ? bias[c + 1] : 0.f;
            if (r0 < M) {
                float v0 = acc[i][j][0] + bb0, v1 = acc[i][j][1] + bb1;
                if (act) { v0 = gelu_exact(v0); v1 = gelu_exact(v1); }
                if (rnd) { v0 = rnd_tf(v0); v1 = rnd_tf(v1); }
                *(float2*)&C[(size_t)r0 * N + c] = make_float2(v0, v1);
            }
            if (r1 < M) {
                float v2 = acc[i][j][2] + bb0, v3 = acc[i][j][3] + bb1;
                if (act) { v2 = gelu_exact(v2); v3 = gelu_exact(v3); }
                if (rnd) { v2 = rnd_tf(v2); v3 = rnd_tf(v3); }
                *(float2*)&C[(size_t)r1 * N + c] = make_float2(v2, v3);
            }
        }
    }
}

#define GEMM128_SMEM (3 * (AS_BUF + G_BK * 136) * 4)   // 107520
#define GEMM160_SMEM (2 * (AS_BUF + G_BK * 168) * 4)   // 79872

// ---------------------------------------------------------------------------
// Split-K reduce: out = p0 + p1 + bias + res   (N = N_STATE columns)
// ---------------------------------------------------------------------------
__global__ void splitk_reduce(const float* __restrict__ p0,
                              const float* __restrict__ p1,
                              const float* __restrict__ bias,
                              const float* __restrict__ res,
                              float* __restrict__ out) {
    int i = blockIdx.x * blockDim.x + threadIdx.x;           // float4 index
    const int total4 = S_LEN * N_STATE / 4;
    if (i >= total4) return;
    float4 a = ((const float4*)p0)[i];
    float4 b = ((const float4*)p1)[i];
    float4 r = ((const float4*)res)[i];
    int c = (i * 4) % N_STATE;
    float4 bb = *(const float4*)&bias[c];
    float4 o;
    o.x = a.x + b.x + bb.x + r.x;
    o.y = a.y + b.y + bb.y + r.y;
    o.z = a.z + b.z + bb.z + r.z;
    o.w = a.w + b.w + bb.w + r.w;
    ((float4*)out)[i] = o;
}

// ---------------------------------------------------------------------------
// Fused flash attention (non-causal), k-dim permutation trick.
// Block = (q-tile of 128, head), 256 threads = 8 warps, warp owns 16 q rows.
//  * QK^T: Q frags load dims (2t, 2t+1); K B-frags = one LDS.64 whose halves
//    land directly in bf[0]/bf[1] (operand order -> no repack).
//  * P.V : S/P C-fragment IS the PV A-fragment (P never touches smem).
// *** 3-stage K/V pipeline: prefetch TWO tiles ahead, CP_WAIT(1) so the
// needed tile is complete while the newest load stays in flight — removes
// the per-tile load-latency exposure of the old CP_WAIT(0) scheme.
// Buffer (kt+2)%3 was consumed at tile kt-1; the barrier at kt protects it.
// smem = 3*(64*72 + 64*68) words = 107520 B -> 2 CTAs/SM.
// ---------------------------------------------------------------------------
#define KB_STRIDE 72
#define VB_STRIDE 68
#define KBUF_W (64 * KB_STRIDE)               // 4608
#define VBUF_W (64 * VB_STRIDE)               // 4352
#define AT_STAGE_W (KBUF_W + VBUF_W)          // 8960
#define ATTN_SMEM_BYTES (3 * AT_STAGE_W * 4)  // 107520

__global__ __launch_bounds__(256, 2)
void attn_kernel(const float* __restrict__ qp, const float* __restrict__ kp,
                 const float* __restrict__ vp, float* __restrict__ out) {
    extern __shared__ uint32_t smn[];

    int qt = blockIdx.x;
    int h  = blockIdx.y;
    int tid = threadIdx.x, warp = tid >> 5, lane = tid & 31;
    int g = lane >> 2, t = lane & 3;
    int qrow0 = qt * 128 + warp * 16;
    uint32_t sbase = (uint32_t)__cvta_generic_to_shared(smn);

    // ---- preload Q fragments with permuted k: word0<->dim 2t, word2<->2t+1 ----
    uint32_t qf[8][4];
    {
        int rA = qrow0 + g, rB = qrow0 + g + 8;
        bool okA = rA < S_LEN, okB = rB < S_LEN;
        const float* qA = qp + (size_t)rA * N_STATE + h * D_HEAD;
        const float* qB = qp + (size_t)rB * N_STATE + h * D_HEAD;
#pragma unroll
        for (int ks = 0; ks < 8; ks++) {
            int d0 = ks * 8 + 2 * t;
            float a0 = okA ? qA[d0]     : 0.f;
            float a1 = okB ? qB[d0]     : 0.f;
            float a2 = okA ? qA[d0 + 1] : 0.f;
            float a3 = okB ? qB[d0 + 1] : 0.f;
            qf[ks][0] = __float_as_uint(a0 * 0.125f);
            qf[ks][1] = __float_as_uint(a1 * 0.125f);
            qf[ks][2] = __float_as_uint(a2 * 0.125f);
            qf[ks][3] = __float_as_uint(a3 * 0.125f);
        }
    }

    float of[8][4];
#pragma unroll
    for (int j = 0; j < 8; j++)
#pragma unroll
        for (int r = 0; r < 4; r++) of[j][r] = 0.f;
    float m0 = -1e30f, m1 = -1e30f, l0 = 0.f, l1 = 0.f;

    int lrow = tid >> 4;            // 0..15
    int lc4  = (tid & 15) * 4;      // 0..60
    const float* kpb = kp + h * D_HEAD + lc4;
    const float* vpb = vp + h * D_HEAD + lc4;

    auto issue = [&](int kt, int buf) {
        uint32_t kbase = sbase + (buf * AT_STAGE_W) * 4;
        uint32_t vbase = kbase + KBUF_W * 4;
#pragma unroll
        for (int p = 0; p < 4; p++) {
            int row = lrow + p * 16;
            int gk = kt * 64 + row;
            cp16(kbase + (row * KB_STRIDE + lc4) * 4,
                 kpb + (size_t)gk * N_STATE, gk < S_LEN);
        }
#pragma unroll
        for (int p = 0; p < 4; p++) {
            int row = lrow + p * 16;
            int gk = kt * 64 + row;
            cp16(vbase + (row * VB_STRIDE + lc4) * 4,
                 vpb + (size_t)gk * N_STATE, gk < S_LEN);
        }
        CP_COMMIT();
    };

    issue(0, 0);
    issue(1, 1);

    int buf = 0;
    for (int kt = 0; kt < NKT; kt++) {
        if (kt + 1 < NKT) { CP_WAIT(1); }   // tile kt resident; kt+1 may fly
        else              { CP_WAIT(0); }
        __syncthreads();   // all warps done with tile kt-1's buffer
        if (kt + 2 < NKT) {
            int nb = buf + 2; if (nb >= 3) nb -= 3;
            issue(kt + 2, nb);              // overlaps 2 tiles of compute
        }

        const uint32_t* Kb = smn + buf * AT_STAGE_W;
        const uint32_t* Vb = Kb + KBUF_W;

        // ---- S = Q * K^T  (16 x 64 per warp); B-frag = one LDS.64 ----
        float sacc[8][4];
#pragma unroll
        for (int j = 0; j < 8; j++)
#pragma unroll
            for (int r = 0; r < 4; r++) sacc[j][r] = 0.f;

#pragma unroll
        for (int ks = 0; ks < 8; ks++) {
#pragma unroll
            for (int j = 0; j < 8; j++) {
                uint2 kb = *(const uint2*)&Kb[(j * 8 + g) * KB_STRIDE + ks * 8 + 2 * t];
                uint32_t bf[2] = {kb.x, kb.y};
                mma_tf32(sacc[j], qf[ks], bf);
            }
        }

        // ---- mask padded keys (only last tile) ----
        if (kt == NKT - 1) {
#pragma unroll
            for (int j = 0; j < 8; j++) {
                int c = j * 8 + 2 * t;
                if (1472 + c     >= S_LEN) { sacc[j][0] = -1e30f; sacc[j][2] = -1e30f; }
                if (1472 + c + 1 >= S_LEN) { sacc[j][1] = -1e30f; sacc[j][3] = -1e30f; }
            }
        }

        // ---- online softmax ----
        float tm0 = -1e30f, tm1 = -1e30f;
#pragma unroll
        for (int j = 0; j < 8; j++) {
            tm0 = fmaxf(tm0, fmaxf(sacc[j][0], sacc[j][1]));
            tm1 = fmaxf(tm1, fmaxf(sacc[j][2], sacc[j][3]));
        }
        tm0 = fmaxf(tm0, __shfl_xor_sync(0xffffffffu, tm0, 1));
        tm0 = fmaxf(tm0, __shfl_xor_sync(0xffffffffu, tm0, 2));
        tm1 = fmaxf(tm1, __shfl_xor_sync(0xffffffffu, tm1, 1));
        tm1 = fmaxf(tm1, __shfl_xor_sync(0xffffffffu, tm1, 2));

        float nm0 = fmaxf(m0, tm0), nm1 = fmaxf(m1, tm1);
        float c0 = __expf(m0 - nm0), c1 = __expf(m1 - nm1);
        l0 *= c0; l1 *= c1;
#pragma unroll
        for (int j = 0; j < 8; j++) {
            of[j][0] *= c0; of[j][1] *= c0;
            of[j][2] *= c1; of[j][3] *= c1;
        }
        m0 = nm0; m1 = nm1;

        // ---- P = exp(S - m), tf32-rounded, kept in the sacc registers ----
        float ps0 = 0.f, ps1 = 0.f;
#pragma unroll
        for (int j = 0; j < 8; j++) {
            float p0 = rnd_tf(__expf(sacc[j][0] - nm0));
            float p1 = rnd_tf(__expf(sacc[j][1] - nm0));
            float p2 = rnd_tf(__expf(sacc[j][2] - nm1));
            float p3 = rnd_tf(__expf(sacc[j][3] - nm1));
            sacc[j][0] = p0; sacc[j][1] = p1; sacc[j][2] = p2; sacc[j][3] = p3;
            ps0 += p0 + p1; ps1 += p2 + p3;
        }
        ps0 += __shfl_xor_sync(0xffffffffu, ps0, 1);
        ps0 += __shfl_xor_sync(0xffffffffu, ps0, 2);
        ps1 += __shfl_xor_sync(0xffffffffu, ps1, 1);
        ps1 += __shfl_xor_sync(0xffffffffu, ps1, 2);
        l0 += ps0; l1 += ps1;

        // ---- O += P * V : A-fragment comes straight from sacc registers ----
#pragma unroll
        for (int ksJ = 0; ksJ < 8; ksJ++) {     // key block = S column block
            uint32_t af[4];
            af[0] = __float_as_uint(sacc[ksJ][0]);   // P[g   ][key 2t]
            af[1] = __float_as_uint(sacc[ksJ][2]);   // P[g+8 ][key 2t]
            af[2] = __float_as_uint(sacc[ksJ][1]);   // P[g   ][key 2t+1]
            af[3] = __float_as_uint(sacc[ksJ][3]);   // P[g+8 ][key 2t+1]
            const uint32_t* vrow = Vb + (ksJ * 8 + 2 * t) * VB_STRIDE + g;
#pragma unroll
            for (int j = 0; j < 8; j++) {
                uint32_t bf[2];
                bf[0] = vrow[j * 8];                 // V[key 2t  ][dim j8+g]
                bf[1] = vrow[VB_STRIDE + j * 8];     // V[key 2t+1][dim j8+g]
                mma_tf32(of[j], af, bf);
            }
        }
        if (++buf == 3) buf = 0;
    }

    // ---- finalize + store (rounded: feeds O-proj as A operand) ----
    float inv0 = 1.0f / l0, inv1 = 1.0f / l1;
    int r0 = qrow0 + g, r1 = qrow0 + g + 8;
#pragma unroll
    for (int j = 0; j < 8; j++) {
        int c = h * D_HEAD + j * 8 + 2 * t;
        if (r0 < S_LEN)
            *(float2*)&out[(size_t)r0 * N_STATE + c] =
                make_float2(rnd_tf(of[j][0] * inv0), rnd_tf(of[j][1] * inv0));
        if (r1 < S_LEN)
            *(float2*)&out[(size_t)r1 * N_STATE + c] =
                make_float2(rnd_tf(of[j][2] * inv1), rnd_tf(of[j][3] * inv1));
    }
}

// ---------------------------------------------------------------------------
// Launch: 8 kernels on the default stream (graph-capturable, alloc-free)
// ---------------------------------------------------------------------------
extern "C" void kernel_launch(void* const* d_in, const int* in_sizes, int n_in,
                              void* d_out, int out_size) {
    (void)in_sizes; (void)n_in; (void)out_size;

    const float* x    = (const float*)d_in[0];
    const float* Wq   = (const float*)d_in[1];
    const float* bq   = (const float*)d_in[2];
    const float* Wk   = (const float*)d_in[3];
    const float* Wv   = (const float*)d_in[4];
    const float* bv   = (const float*)d_in[5];
    const float* Wo   = (const float*)d_in[6];
    const float* bo   = (const float*)d_in[7];
    const float* ln1g = (const float*)d_in[8];
    const float* ln1b = (const float*)d_in[9];
    const float* ln2g = (const float*)d_in[10];
    const float* ln2b = (const float*)d_in[11];
    const float* W1   = (const float*)d_in[12];
    const float* b1   = (const float*)d_in[13];
    const float* W2   = (const float*)d_in[14];
    const float* b2   = (const float*)d_in[15];
    float* out = (float*)d_out;

    Scratch* sc = nullptr;
    cudaGetSymbolAddress((void**)&sc, g_scratch);

    cudaFuncSetAttribute(gemm_tf32<128, 3>,
                         cudaFuncAttributeMaxDynamicSharedMemorySize,
                         GEMM128_SMEM);
    cudaFuncSetAttribute(gemm_tf32<160, 2>,
                         cudaFuncAttributeMaxDynamicSharedMemorySize,
                         GEMM160_SMEM);
    cudaFuncSetAttribute(attn_kernel,
                         cudaFuncAttributeMaxDynamicSharedMemorySize,
                         ATTN_SMEM_BYTES);

    dim3 gQKV (N_STATE / 160, (S_LEN + G_BM - 1) / G_BM, 3);   // (8,12,3)=288
    dim3 gSpl (N_STATE / 128, (S_LEN + G_BM - 1) / G_BM, 2);   // (10,12,2)=240
    dim3 gMLP1(N_MLP  / 160, (S_LEN + G_BM - 1) / G_BM, 1);    // (32,12,1)=384
    const int red_grid = (S_LEN * N_STATE / 4 + 255) / 256;

    // LN1 (output tf32-rounded)
    ln_kernel<<<S_LEN, 256>>>(x, ln1g, ln1b, sc->h);

    // QKV projections: BN=160 -> 288 CTAs = ONE wave at 2 CTAs/SM
    GemmBatch qkv;
    qkv.B[0] = Wq; qkv.bias[0] = bq;      qkv.C[0] = sc->q;
    qkv.B[1] = Wk; qkv.bias[1] = nullptr; qkv.C[1] = sc->k;
    qkv.B[2] = Wv; qkv.bias[2] = bv;      qkv.C[2] = sc->v;
    gemm_tf32<160, 2><<<gQKV, 256, GEMM160_SMEM>>>(sc->h, qkv,
        S_LEN, N_STATE, N_STATE, /*lda=*/N_STATE, /*aOffK=*/0, 0, /*rnd=*/1);

    // attention (output tf32-rounded; 3-stage K/V pipeline)
    attn_kernel<<<dim3(12, N_HEAD), 256, ATTN_SMEM_BYTES>>>(sc->q, sc->k, sc->v, sc->attn);

    // O-proj split-K x2 -> partials, then fused reduce(+bias+residual)+LN2
    GemmBatch opr;
    opr.B[0] = Wo;                         opr.bias[0] = nullptr; opr.C[0] = sc->part0;
    opr.B[1] = Wo + (size_t)640 * N_STATE; opr.bias[1] = nullptr; opr.C[1] = sc->part1;
    opr.B[2] = nullptr; opr.bias[2] = nullptr; opr.C[2] = nullptr;
    gemm_tf32<128, 3><<<gSpl, 256, GEMM128_SMEM>>>(sc->attn, opr,
        S_LEN, N_STATE, /*K=*/640, /*lda=*/N_STATE, /*aOffK=*/640, 0, 0);
    reduce_ln_kernel<<<S_LEN, 256>>>(sc->part0, sc->part1, bo, x,
                                     ln2g, ln2b, sc->x1, sc->h);

    // MLP1 (+exact GELU): BN=160 -> 384 CTAs (1.30 waves vs 1.62)
    GemmBatch m1;
    m1.B[0] = W1; m1.bias[0] = b1; m1.C[0] = sc->h2;
    m1.B[1] = m1.B[2] = nullptr; m1.bias[1] = m1.bias[2] = nullptr;
    m1.C[1] = m1.C[2] = nullptr;
    gemm_tf32<160, 2><<<gMLP1, 256, GEMM160_SMEM>>>(sc->h, m1,
        S_LEN, N_MLP, N_STATE, /*lda=*/N_STATE, /*aOffK=*/0, /*act=*/1, /*rnd=*/1);

    // MLP2 split-K x2 -> partials, then reduce (+bias +residual x1) -> out
    GemmBatch m2;
    m2.B[0] = W2;                          m2.bias[0] = nullptr; m2.C[0] = sc->part0;
    m2.B[1] = W2 + (size_t)2560 * N_STATE; m2.bias[1] = nullptr; m2.C[1] = sc->part1;
    m2.B[2] = nullptr; m2.bias[2] = nullptr; m2.C[2] = nullptr;
    gemm_tf32<128, 3><<<gSpl, 256, GEMM128_SMEM>>>(sc->h2, m2,
        S_LEN, N_STATE, /*K=*/2560, /*lda=*/N_MLP, /*aOffK=*/2560, 0, 0);
    splitk_reduce<<<red_grid, 256>>>(sc->part0, sc->part1, b2, sc->x1, out);
}